// round 3
// baseline (speedup 1.0000x reference)
#include <cuda_runtime.h>
#include <stdint.h>
#include <math.h>

// ---------------------------------------------------------------------------
// ProposalLayer: decode -> clip -> min-size filter -> top-12000 -> NMS(0.7)
//                -> first 2000 kept boxes (zero padded)
// ---------------------------------------------------------------------------

#define NMAX   147456
#define NPRE   12000
#define NPOST  2000
#define CAP    16384
#define SORT_SZ 16384
#define NMS_T  0.7f

// ------------------------- scratch (device globals) ------------------------
__device__ unsigned int       g_keys[NMAX];
__device__ float4             g_boxes[NMAX];
__device__ int                g_hist1[65536];
__device__ int                g_hist2[65536];
__device__ unsigned int       g_T;
__device__ int                g_C1;
__device__ int                g_flag;          // set if fewer than NPRE valid
__device__ unsigned int       g_kthKey;
__device__ int                g_candCount;
__device__ unsigned long long g_cand[CAP];
__device__ float4             g_topBox[NPRE];
__device__ float              g_topArea[NPRE];
__device__ int                g_validTop;

// ------------------------------- K0: zero ----------------------------------
__global__ void k_zero(float* __restrict__ out) {
    int i = blockIdx.x * blockDim.x + threadIdx.x;
    int stride = gridDim.x * blockDim.x;
    for (int k = i; k < 65536; k += stride) { g_hist1[k] = 0; g_hist2[k] = 0; }
    for (int k = i; k < NPOST * 4; k += stride) out[k] = 0.0f;
    if (i == 0) {
        g_candCount = 0;
        g_flag      = 0;
        g_validTop  = NPRE;
        g_T         = 0;
        g_C1        = 0;
        g_kthKey    = 0x80000000u;   // fallback: gather all valid
    }
}

// --------------------- K1: decode + clip + key + hist1 ---------------------
__global__ void k_decode(const float* __restrict__ anc,
                         const float* __restrict__ off,
                         const float* __restrict__ sc,
                         const int* __restrict__ ph,
                         const int* __restrict__ pw,
                         const int* __restrict__ ps,
                         int n) {
    int i = blockIdx.x * blockDim.x + threadIdx.x;
    if (i >= n) return;

    float H = (float)ph[0];
    float W = (float)pw[0];
    float minsz = __fmul_rn(16.0f, (float)ps[0]);

    float a0 = anc[4 * i + 0], a1 = anc[4 * i + 1];
    float a2 = anc[4 * i + 2], a3 = anc[4 * i + 3];
    float o0 = off[4 * i + 0], o1 = off[4 * i + 1];
    float o2 = off[4 * i + 2], o3 = off[4 * i + 3];

    // match reference arithmetic exactly (no FMA contraction)
    float ah  = __fsub_rn(a2, a0);
    float aw  = __fsub_rn(a3, a1);
    float acy = __fadd_rn(a0, __fmul_rn(0.5f, ah));
    float acx = __fadd_rn(a1, __fmul_rn(0.5f, aw));
    float cy  = __fadd_rn(__fmul_rn(o0, ah), acy);
    float cx  = __fadd_rn(__fmul_rn(o1, aw), acx);
    float h   = __fmul_rn(expf(o2), ah);
    float w   = __fmul_rn(expf(o3), aw);

    float y1 = __fsub_rn(cy, __fmul_rn(0.5f, h));
    float x1 = __fsub_rn(cx, __fmul_rn(0.5f, w));
    float y2 = __fadd_rn(cy, __fmul_rn(0.5f, h));
    float x2 = __fadd_rn(cx, __fmul_rn(0.5f, w));

    y1 = fminf(fmaxf(y1, 0.0f), H);
    x1 = fminf(fmaxf(x1, 0.0f), W);
    y2 = fminf(fmaxf(y2, 0.0f), H);
    x2 = fminf(fmaxf(x2, 0.0f), W);

    float rh = __fsub_rn(y2, y1);
    float rw = __fsub_rn(x2, x1);
    bool valid = (rh >= minsz) && (rw >= minsz);

    unsigned key = 0u;
    if (valid) {
        unsigned u = __float_as_uint(sc[i]);
        key = (u & 0x80000000u) ? ~u : (u | 0x80000000u);
        if (key == 0u) key = 1u;   // reserve 0 for "invalid"
    }
    g_keys[i]  = key;
    g_boxes[i] = make_float4(y1, x1, y2, x2);
    if (key) atomicAdd(&g_hist1[key >> 16], 1);
}

// -------------------- K2: find threshold bin (16 high bits) ----------------
__global__ void k_find1() {
    __shared__ int part[1024];
    int t = threadIdx.x;
    int base = t * 64;
    int s = 0;
#pragma unroll 4
    for (int k = 0; k < 64; k++) s += g_hist1[base + k];
    part[t] = s;
    __syncthreads();
    // inclusive suffix sum (Hillis-Steele)
    for (int offs = 1; offs < 1024; offs <<= 1) {
        int v = part[t] + ((t + offs < 1024) ? part[t + offs] : 0);
        __syncthreads();
        part[t] = v;
        __syncthreads();
    }
    int Sincl = part[t];
    int Sexcl = Sincl - s;
    if (t == 0 && part[0] < NPRE) g_flag = 1;   // fewer than NPRE valid
    if (Sexcl < NPRE && Sincl >= NPRE) {
        int cum = Sexcl;
        for (int b = base + 63; b >= base; b--) {
            int hb = g_hist1[b];
            cum += hb;
            if (cum >= NPRE) {
                g_T  = (unsigned)b;
                g_C1 = cum - hb;
                break;
            }
        }
    }
}

// ------------------ K3: second-level histogram (16 low bits) ---------------
__global__ void k_hist2(int n) {
    int i = blockIdx.x * blockDim.x + threadIdx.x;
    if (i >= n) return;
    unsigned key = g_keys[i];
    if (key && (key >> 16) == g_T) atomicAdd(&g_hist2[key & 0xFFFFu], 1);
}

// ----------------------- K4: exact 32-bit K-th key -------------------------
__global__ void k_find2() {
    if (g_flag) return;    // kthKey stays at 0x80000000 (gather all valid)
    __shared__ int part[1024];
    int t = threadIdx.x;
    int C1 = g_C1;
    int base = t * 64;
    int s = 0;
#pragma unroll 4
    for (int k = 0; k < 64; k++) s += g_hist2[base + k];
    part[t] = s;
    __syncthreads();
    for (int offs = 1; offs < 1024; offs <<= 1) {
        int v = part[t] + ((t + offs < 1024) ? part[t + offs] : 0);
        __syncthreads();
        part[t] = v;
        __syncthreads();
    }
    int Sincl = part[t];
    int Sexcl = Sincl - s;
    if (C1 + Sexcl < NPRE && C1 + Sincl >= NPRE) {
        int cum = C1 + Sexcl;
        for (int b = base + 63; b >= base; b--) {
            cum += g_hist2[b];
            if (cum >= NPRE) {
                g_kthKey = (g_T << 16) | (unsigned)b;
                break;
            }
        }
    }
}

// ----------------------------- K5: gather ----------------------------------
__global__ void k_gather(int n) {
    int i = blockIdx.x * blockDim.x + threadIdx.x;
    if (i >= n) return;
    unsigned key = g_keys[i];
    if (key && key >= g_kthKey) {
        int p = atomicAdd(&g_candCount, 1);
        if (p < CAP) {
            // composite: score key desc, then index asc (top_k tie-break)
            g_cand[p] = ((unsigned long long)key << 32) |
                        (unsigned long long)(0xFFFFFFFFu - (unsigned)i);
        }
    }
}

// ---------------- K6: one-block bitonic sort of 16384 u64 keys -------------
__global__ void k_sort() {
    extern __shared__ unsigned long long s[];
    int tid = threadIdx.x;
    int m = g_candCount;
    if (m > CAP) m = CAP;
    for (int k = tid; k < SORT_SZ; k += 1024)
        s[k] = (k < m) ? g_cand[k] : 0ull;
    __syncthreads();

    for (int k = 2; k <= SORT_SZ; k <<= 1) {
        for (int j = k >> 1; j > 0; j >>= 1) {
            for (int i = tid; i < SORT_SZ; i += 1024) {
                int ixj = i ^ j;
                if (ixj > i) {
                    unsigned long long a = s[i];
                    unsigned long long b = s[ixj];
                    // descending overall
                    bool doSwap = ((i & k) == 0) ? (a < b) : (a > b);
                    if (doSwap) { s[i] = b; s[ixj] = a; }
                }
            }
            __syncthreads();
        }
    }

    // emit top NPRE: boxes + areas; find first invalid rank
    for (int r = tid; r < NPRE; r += 1024) {
        unsigned long long v = s[r];
        unsigned key = (unsigned)(v >> 32);
        if (key == 0u) {
            atomicMin(&g_validTop, r);
        } else {
            unsigned idx = 0xFFFFFFFFu - (unsigned)v;
            float4 b = g_boxes[idx];
            g_topBox[r]  = b;
            g_topArea[r] = __fmul_rn(__fsub_rn(b.z, b.x), __fsub_rn(b.w, b.y));
        }
    }
}

// --------------------------- IoU (reference-exact) -------------------------
__device__ __forceinline__ bool iou_gt(float4 a, float aa, float4 b, float ab) {
    float ty = fmaxf(a.x, b.x);
    float tx = fmaxf(a.y, b.y);
    float by = fminf(a.z, b.z);
    float bx = fminf(a.w, b.w);
    float hh = fmaxf(__fsub_rn(by, ty), 0.0f);
    float ww = fmaxf(__fsub_rn(bx, tx), 0.0f);
    float inter = __fmul_rn(hh, ww);
    float uni = __fsub_rn(__fadd_rn(aa, ab), inter);
    float iou = __fdiv_rn(inter, fmaxf(uni, 1e-9f));
    return iou > NMS_T;
}

// ------------- K7: greedy NMS, early-stop at NPOST kept, 1 block -----------
__global__ void __launch_bounds__(1024, 1) k_nms(float* __restrict__ out) {
    __shared__ float4 kb[NPOST];
    __shared__ float  ka[NPOST];
    __shared__ float4 cb[64];
    __shared__ float  ca[64];
    __shared__ unsigned long long lmask[64];
    __shared__ int    supf[64];
    __shared__ unsigned long long sKeepLocal;
    __shared__ int    sKept;

    int tid  = threadIdx.x;
    int lane = tid & 31;
    int wid  = tid >> 5;
    int validTop = g_validTop;

    int kept = 0;
    for (int base = 0; base < NPRE && kept < NPOST; base += 64) {
        int cn = validTop - base;
        if (cn > 64) cn = 64;
        if (cn <= 0) break;

        if (tid < 64) {
            supf[tid]  = 0;
            lmask[tid] = 0ull;
            if (tid < cn) {
                cb[tid] = g_topBox[base + tid];
                ca[tid] = g_topArea[base + tid];
            }
        }
        __syncthreads();

        // (a) suppressed by any previously kept box? (warp per chunk box)
        for (int i = wid; i < cn; i += 32) {
            float4 bi = cb[i];
            float  ai = ca[i];
            bool any = false;
            for (int j = lane; j < kept; j += 32) {
                if (iou_gt(bi, ai, kb[j], ka[j])) { any = true; break; }
            }
            bool w = __any_sync(0xffffffffu, any);
            if (w && lane == 0) supf[i] = 1;
        }

        // (b) intra-chunk pairwise mask
        for (int p = tid; p < 64 * 64; p += 1024) {
            int i = p >> 6;
            int j = p & 63;
            if (i < cn && j < i) {
                if (iou_gt(cb[i], ca[i], cb[j], ca[j]))
                    atomicOr(&lmask[i], 1ull << j);
            }
        }
        __syncthreads();

        // (c) scalar sequential resolve of the 64-box chunk
        if (tid == 0) {
            unsigned long long kl = 0ull;
            int kc = kept;
            for (int i = 0; i < cn && kc < NPOST; i++) {
                if (!supf[i] && !(lmask[i] & kl)) {
                    kl |= 1ull << i;
                    kc++;
                }
            }
            sKeepLocal = kl;
            sKept = kc;
        }
        __syncthreads();

        // (d) append kept boxes; write output in kept order
        unsigned long long kl = sKeepLocal;
        if (tid < cn && ((kl >> tid) & 1ull)) {
            int pos = kept + __popcll(kl & ((1ull << tid) - 1ull));
            kb[pos] = cb[tid];
            ka[pos] = ca[tid];
            ((float4*)out)[pos] = cb[tid];
        }
        __syncthreads();
        kept = sKept;
        __syncthreads();
    }
}

// ------------------------------- launcher ----------------------------------
extern "C" void kernel_launch(void* const* d_in, const int* in_sizes, int n_in,
                              void* d_out, int out_size) {
    const float* anchors = (const float*)d_in[0];
    const float* offsets = (const float*)d_in[1];
    const float* scores  = (const float*)d_in[2];
    const int*   ph      = (const int*)d_in[3];
    const int*   pw      = (const int*)d_in[4];
    const int*   ps      = (const int*)d_in[5];
    float* out = (float*)d_out;

    int n = in_sizes[2];
    if (n > NMAX) n = NMAX;
    int nb = (n + 255) / 256;

    k_zero<<<256, 256>>>(out);
    k_decode<<<nb, 256>>>(anchors, offsets, scores, ph, pw, ps, n);
    k_find1<<<1, 1024>>>();
    k_hist2<<<nb, 256>>>(n);
    k_find2<<<1, 1024>>>();
    k_gather<<<nb, 256>>>(n);

    static bool attr_set = false;
    if (!attr_set) {
        cudaFuncSetAttribute(k_sort, cudaFuncAttributeMaxDynamicSharedMemorySize,
                             SORT_SZ * (int)sizeof(unsigned long long));
        attr_set = true;
    }
    k_sort<<<1, 1024, SORT_SZ * sizeof(unsigned long long)>>>();
    k_nms<<<1, 1024>>>(out);
}

// round 5
// speedup vs baseline: 2.2164x; 2.2164x over previous
#include <cuda_runtime.h>
#include <cub/cub.cuh>
#include <stdint.h>
#include <math.h>

// ---------------------------------------------------------------------------
// ProposalLayer: decode -> clip -> min-size filter -> top-12000 -> NMS(0.7)
//                -> first 2000 kept boxes (zero padded)
// R3: cub radix sort (was 1-block bitonic) + precomputed chip-wide NMS bitmask
//     (was 1-block IoU recompute). Only O(N) greedy resolve stays serial.
// ---------------------------------------------------------------------------

#define NMAX    147456
#define NPRE    12000
#define NPOST   2000
#define CAP     16384
#define NMS_T   0.7f
#define WPR     188          // u64 words per mask row (ceil(12000/64))
#define TOPPAD  12032        // 188*64, padded top-box array
#define B1      4096         // stage-1 NMS coverage (64 chunks)
#define CUB_TEMP_CAP (8u << 20)

// ------------------------- scratch (device globals) ------------------------
__device__ unsigned int       g_keys[NMAX];
__device__ float4             g_boxes[NMAX];
__device__ int                g_hist1[65536];
__device__ int                g_hist2[65536];
__device__ unsigned int       g_T;
__device__ int                g_C1;
__device__ int                g_flag;
__device__ unsigned int       g_kthKey;
__device__ int                g_candCount;
__device__ unsigned long long g_cand[CAP];
__device__ unsigned long long g_sorted[CAP];
__device__ unsigned char      g_cubTemp[CUB_TEMP_CAP];
__device__ float4             g_topBox[TOPPAD];   // never-written tail stays 0
__device__ float              g_topArea[TOPPAD];
__device__ int                g_validTop;
__device__ unsigned long long g_mask[(size_t)NPRE * WPR];   // ~18 MB
__device__ int                g_kept;
__device__ int                g_needMore;
__device__ unsigned long long g_keptMaskG[WPR];

// ------------------------------- K0: zero ----------------------------------
__global__ void k_zero(float* __restrict__ out) {
    int i = blockIdx.x * blockDim.x + threadIdx.x;
    int stride = gridDim.x * blockDim.x;
    for (int k = i; k < 65536; k += stride) { g_hist1[k] = 0; g_hist2[k] = 0; }
    for (int k = i; k < NPOST * 4; k += stride) out[k] = 0.0f;
    for (int k = i; k < CAP; k += stride) g_cand[k] = 0ull;
    if (i == 0) {
        g_candCount = 0;
        g_flag      = 0;
        g_validTop  = NPRE;
        g_T         = 0;
        g_C1        = 0;
        g_kthKey    = 1u;      // fallback: gather all valid (only if <NPRE valid)
        g_needMore  = 0;
        g_kept      = 0;
    }
}

// --------------------- K1: decode + clip + key + hist1 ---------------------
__global__ void k_decode(const float* __restrict__ anc,
                         const float* __restrict__ off,
                         const float* __restrict__ sc,
                         const int* __restrict__ ph,
                         const int* __restrict__ pw,
                         const int* __restrict__ ps,
                         int n) {
    int i = blockIdx.x * blockDim.x + threadIdx.x;
    if (i >= n) return;

    float H = (float)ph[0];
    float W = (float)pw[0];
    float minsz = __fmul_rn(16.0f, (float)ps[0]);

    float a0 = anc[4 * i + 0], a1 = anc[4 * i + 1];
    float a2 = anc[4 * i + 2], a3 = anc[4 * i + 3];
    float o0 = off[4 * i + 0], o1 = off[4 * i + 1];
    float o2 = off[4 * i + 2], o3 = off[4 * i + 3];

    float ah  = __fsub_rn(a2, a0);
    float aw  = __fsub_rn(a3, a1);
    float acy = __fadd_rn(a0, __fmul_rn(0.5f, ah));
    float acx = __fadd_rn(a1, __fmul_rn(0.5f, aw));
    float cy  = __fadd_rn(__fmul_rn(o0, ah), acy);
    float cx  = __fadd_rn(__fmul_rn(o1, aw), acx);
    float h   = __fmul_rn(expf(o2), ah);
    float w   = __fmul_rn(expf(o3), aw);

    float y1 = __fsub_rn(cy, __fmul_rn(0.5f, h));
    float x1 = __fsub_rn(cx, __fmul_rn(0.5f, w));
    float y2 = __fadd_rn(cy, __fmul_rn(0.5f, h));
    float x2 = __fadd_rn(cx, __fmul_rn(0.5f, w));

    y1 = fminf(fmaxf(y1, 0.0f), H);
    x1 = fminf(fmaxf(x1, 0.0f), W);
    y2 = fminf(fmaxf(y2, 0.0f), H);
    x2 = fminf(fmaxf(x2, 0.0f), W);

    float rh = __fsub_rn(y2, y1);
    float rw = __fsub_rn(x2, x1);
    bool valid = (rh >= minsz) && (rw >= minsz);

    unsigned key = 0u;
    if (valid) {
        unsigned u = __float_as_uint(sc[i]);
        key = (u & 0x80000000u) ? ~u : (u | 0x80000000u);
        if (key == 0u) key = 1u;
    }
    g_keys[i]  = key;
    g_boxes[i] = make_float4(y1, x1, y2, x2);
    if (key) atomicAdd(&g_hist1[key >> 16], 1);
}

// -------------------- K2: find threshold bin (16 high bits) ----------------
__global__ void k_find1() {
    __shared__ int part[1024];
    int t = threadIdx.x;
    int base = t * 64;
    int s = 0;
#pragma unroll 4
    for (int k = 0; k < 64; k++) s += g_hist1[base + k];
    part[t] = s;
    __syncthreads();
    for (int offs = 1; offs < 1024; offs <<= 1) {
        int v = part[t] + ((t + offs < 1024) ? part[t + offs] : 0);
        __syncthreads();
        part[t] = v;
        __syncthreads();
    }
    int Sincl = part[t];
    int Sexcl = Sincl - s;
    if (t == 0 && part[0] < NPRE) g_flag = 1;
    if (Sexcl < NPRE && Sincl >= NPRE) {
        int cum = Sexcl;
        for (int b = base + 63; b >= base; b--) {
            int hb = g_hist1[b];
            cum += hb;
            if (cum >= NPRE) {
                g_T  = (unsigned)b;
                g_C1 = cum - hb;
                break;
            }
        }
    }
}

// ------------------ K3: second-level histogram (16 low bits) ---------------
__global__ void k_hist2(int n) {
    int i = blockIdx.x * blockDim.x + threadIdx.x;
    if (i >= n) return;
    unsigned key = g_keys[i];
    if (key && (key >> 16) == g_T) atomicAdd(&g_hist2[key & 0xFFFFu], 1);
}

// ----------------------- K4: exact 32-bit K-th key -------------------------
__global__ void k_find2() {
    if (g_flag) return;
    __shared__ int part[1024];
    int t = threadIdx.x;
    int C1 = g_C1;
    int base = t * 64;
    int s = 0;
#pragma unroll 4
    for (int k = 0; k < 64; k++) s += g_hist2[base + k];
    part[t] = s;
    __syncthreads();
    for (int offs = 1; offs < 1024; offs <<= 1) {
        int v = part[t] + ((t + offs < 1024) ? part[t + offs] : 0);
        __syncthreads();
        part[t] = v;
        __syncthreads();
    }
    int Sincl = part[t];
    int Sexcl = Sincl - s;
    if (C1 + Sexcl < NPRE && C1 + Sincl >= NPRE) {
        int cum = C1 + Sexcl;
        for (int b = base + 63; b >= base; b--) {
            cum += g_hist2[b];
            if (cum >= NPRE) {
                g_kthKey = (g_T << 16) | (unsigned)b;
                break;
            }
        }
    }
}

// ----------------------------- K5: gather ----------------------------------
__global__ void k_gather(int n) {
    int i = blockIdx.x * blockDim.x + threadIdx.x;
    if (i >= n) return;
    unsigned key = g_keys[i];
    if (key && key >= g_kthKey) {
        int p = atomicAdd(&g_candCount, 1);
        if (p < CAP) {
            // composite: score key desc, then index asc (top_k tie-break)
            g_cand[p] = ((unsigned long long)key << 32) |
                        (unsigned long long)(0xFFFFFFFFu - (unsigned)i);
        }
    }
}

// ------------------- K6: emit sorted top boxes + areas ---------------------
__global__ void k_emit() {
    int r = blockIdx.x * blockDim.x + threadIdx.x;
    if (r >= NPRE) return;
    unsigned long long v = g_sorted[r];
    unsigned key = (unsigned)(v >> 32);
    if (key == 0u) { atomicMin(&g_validTop, r); return; }
    unsigned idx = 0xFFFFFFFFu - (unsigned)v;
    float4 b = g_boxes[idx];
    g_topBox[r]  = b;
    g_topArea[r] = __fmul_rn(__fsub_rn(b.z, b.x), __fsub_rn(b.w, b.y));
}

// --------------------------- IoU (reference-exact) -------------------------
__device__ __forceinline__ bool iou_gt(float4 a, float aa, float4 b, float ab) {
    float ty = fmaxf(a.x, b.x);
    float tx = fmaxf(a.y, b.y);
    float by = fminf(a.z, b.z);
    float bx = fminf(a.w, b.w);
    float hh = fmaxf(__fsub_rn(by, ty), 0.0f);
    float ww = fmaxf(__fsub_rn(bx, tx), 0.0f);
    float inter = __fmul_rn(hh, ww);
    float uni = __fsub_rn(__fadd_rn(aa, ab), inter);
    float iou = __fdiv_rn(inter, fmaxf(uni, 1e-9f));
    return iou > NMS_T;
}

// --------- K7: parallel suppression mask (64x64 tiles, full words) ---------
__global__ void k_mask(int rb0, int gated) {
    if (gated && !g_needMore) return;
    int rb = rb0 + blockIdx.y;
    int cb = blockIdx.x;
    if (cb > rb) return;

    __shared__ float4 cB[64];
    __shared__ float  cA[64];
    int t = threadIdx.x;
    cB[t] = g_topBox[cb * 64 + t];
    cA[t] = g_topArea[cb * 64 + t];
    __syncthreads();

    int row = rb * 64 + t;
    if (row >= NPRE) return;
    float4 rbx = g_topBox[row];
    float  ra  = g_topArea[row];

    unsigned long long word = 0ull;
    int jmax = (cb == rb) ? t : 64;   // strictly j < i
    for (int j = 0; j < jmax; j++)
        if (iou_gt(rbx, ra, cB[j], cA[j])) word |= (1ull << j);
    g_mask[(size_t)row * WPR + cb] = word;
}

// ---------- K8: greedy resolve over precomputed mask (IoU-free) ------------
__global__ void __launch_bounds__(256, 1) k_resolve(int stage, float* __restrict__ out) {
    if (stage && !g_needMore) return;

    __shared__ unsigned long long keptMask[WPR];
    __shared__ unsigned long long diag[64];
    __shared__ int                supPrev[64];
    __shared__ unsigned long long sKl;
    __shared__ int                sKept;

    int tid  = threadIdx.x;
    int lane = tid & 31;
    int warp = tid >> 5;

    int vt = g_validTop;
    int start = stage ? B1 : 0;
    int end   = stage ? vt : (vt < B1 ? vt : B1);
    int kept  = stage ? g_kept : 0;

    if (stage) { for (int w = tid; w < WPR; w += 256) keptMask[w] = g_keptMaskG[w]; }
    else       { for (int w = tid; w < WPR; w += 256) keptMask[w] = 0ull; }
    __syncthreads();

    for (int base = start; base < end && kept < NPOST; base += 64) {
        int cn = end - base; if (cn > 64) cn = 64;
        int cw = base >> 6;

        // suppressed-by-previously-kept: AND mask row with keptMask words
        for (int r = warp; r < cn; r += 8) {
            const unsigned long long* rowp = &g_mask[(size_t)(base + r) * WPR];
            bool any = false;
            for (int w = lane; w < cw; w += 32)
                any |= (rowp[w] & keptMask[w]) != 0ull;
            unsigned bal = __ballot_sync(0xffffffffu, any);
            if (lane == 0) supPrev[r] = (bal != 0u);
        }
        if (tid < cn) diag[tid] = g_mask[(size_t)(base + tid) * WPR + cw];
        __syncthreads();

        // exact sequential greedy within the 64-chunk
        if (tid == 0) {
            unsigned long long kl = 0ull;
            int kc = kept;
            for (int i = 0; i < cn && kc < NPOST; i++) {
                if (!supPrev[i] && !(diag[i] & kl)) { kl |= (1ull << i); kc++; }
            }
            sKl = kl; sKept = kc;
            keptMask[cw] = kl;
        }
        __syncthreads();

        unsigned long long kl = sKl;
        if (tid < cn && ((kl >> tid) & 1ull)) {
            int pos = kept + __popcll(kl & ((1ull << tid) - 1ull));
            ((float4*)out)[pos] = g_topBox[base + tid];
        }
        __syncthreads();
        kept = sKept;
        __syncthreads();
    }

    if (tid == 0) {
        g_kept = kept;
        if (stage == 0) g_needMore = (kept < NPOST && vt > B1) ? 1 : 0;
    }
    for (int w = tid; w < WPR; w += 256) g_keptMaskG[w] = keptMask[w];
}

// ------------------------------- launcher ----------------------------------
extern "C" void kernel_launch(void* const* d_in, const int* in_sizes, int n_in,
                              void* d_out, int out_size) {
    const float* anchors = (const float*)d_in[0];
    const float* offsets = (const float*)d_in[1];
    const float* scores  = (const float*)d_in[2];
    const int*   ph      = (const int*)d_in[3];
    const int*   pw      = (const int*)d_in[4];
    const int*   ps      = (const int*)d_in[5];
    float* out = (float*)d_out;

    int n = in_sizes[2];
    if (n > NMAX) n = NMAX;
    int nb = (n + 255) / 256;

    static bool  s_init = false;
    static void* s_cand = nullptr;
    static void* s_sorted = nullptr;
    static void* s_temp = nullptr;
    if (!s_init) {
        cudaGetSymbolAddress(&s_cand,   g_cand);
        cudaGetSymbolAddress(&s_sorted, g_sorted);
        cudaGetSymbolAddress(&s_temp,   g_cubTemp);
        s_init = true;
    }

    k_zero<<<256, 256>>>(out);
    k_decode<<<nb, 256>>>(anchors, offsets, scores, ph, pw, ps, n);
    k_find1<<<1, 1024>>>();
    k_hist2<<<nb, 256>>>(n);
    k_find2<<<1, 1024>>>();
    k_gather<<<nb, 256>>>(n);

    // cub radix sort of fixed CAP u64 keys (zero pad sorts to the tail)
    size_t tb = 0;
    cub::DeviceRadixSort::SortKeysDescending(
        nullptr, tb,
        (const unsigned long long*)s_cand, (unsigned long long*)s_sorted,
        CAP, 0, 64, (cudaStream_t)0);
    if (tb <= (size_t)CUB_TEMP_CAP) {
        cub::DeviceRadixSort::SortKeysDescending(
            s_temp, tb,
            (const unsigned long long*)s_cand, (unsigned long long*)s_sorted,
            CAP, 0, 64, (cudaStream_t)0);
    }

    k_emit<<<(NPRE + 255) / 256, 256>>>();

    // stage-1 NMS mask: first B1 ranks (always)
    k_mask<<<dim3(B1 / 64, B1 / 64), 64>>>(0, 0);
    k_resolve<<<1, 256>>>(0, out);

    // stage-2 (rare): remaining ranks, gated on g_needMore
    k_mask<<<dim3(WPR, WPR - B1 / 64), 64>>>(B1 / 64, 1);
    k_resolve<<<1, 256>>>(1, out);
}

// round 6
// speedup vs baseline: 2.9459x; 1.3292x over previous
#include <cuda_runtime.h>
#include <stdint.h>
#include <math.h>

// ---------------------------------------------------------------------------
// ProposalLayer: decode -> clip -> min-size filter -> top-12000 -> NMS(0.7)
//                -> first 2000 kept boxes (zero padded)
// R5: cub sort -> O(m^2) brute-force rank+scatter (keys unique), 1 kernel.
//     resolve widened to 1024 threads. int4 histogram scans. 11 launches.
// ---------------------------------------------------------------------------

#define NMAX    147456
#define NPRE    12000
#define NPOST   2000
#define CAP     16384
#define NMS_T   0.7f
#define WPR     188          // u64 words per mask row (ceil(12000/64))
#define TOPPAD  12032        // 188*64, padded top-box array
#define B1      4096         // stage-1 NMS coverage (64 chunks)

// ------------------------- scratch (device globals) ------------------------
__device__ unsigned int       g_keys[NMAX];
__device__ float4             g_boxes[NMAX];
__device__ int                g_hist1[65536];
__device__ int                g_hist2[65536];
__device__ unsigned int       g_T;
__device__ int                g_C1;
__device__ int                g_flag;
__device__ unsigned int       g_kthKey;
__device__ int                g_candCount;
__device__ unsigned long long g_cand[CAP];
__device__ float4             g_topBox[TOPPAD];
__device__ float              g_topArea[TOPPAD];
__device__ int                g_validTop;
__device__ unsigned long long g_mask[(size_t)NPRE * WPR];   // ~18 MB
__device__ int                g_kept;
__device__ int                g_needMore;
__device__ unsigned long long g_keptMaskG[WPR];

// ------------------------------- K0: zero ----------------------------------
__global__ void k_zero(float* __restrict__ out) {
    int i = blockIdx.x * blockDim.x + threadIdx.x;
    int stride = gridDim.x * blockDim.x;
    for (int k = i; k < 65536; k += stride) { g_hist1[k] = 0; g_hist2[k] = 0; }
    for (int k = i; k < NPOST * 4; k += stride) out[k] = 0.0f;
    if (i == 0) {
        g_candCount = 0;
        g_flag      = 0;
        g_T         = 0;
        g_C1        = 0;
        g_kthKey    = 1u;      // fallback: gather all valid (only if <NPRE valid)
        g_needMore  = 0;
        g_kept      = 0;
    }
}

// --------------------- K1: decode + clip + key + hist1 ---------------------
__global__ void k_decode(const float* __restrict__ anc,
                         const float* __restrict__ off,
                         const float* __restrict__ sc,
                         const int* __restrict__ ph,
                         const int* __restrict__ pw,
                         const int* __restrict__ ps,
                         int n) {
    int i = blockIdx.x * blockDim.x + threadIdx.x;
    if (i >= n) return;

    float H = (float)ph[0];
    float W = (float)pw[0];
    float minsz = __fmul_rn(16.0f, (float)ps[0]);

    float a0 = anc[4 * i + 0], a1 = anc[4 * i + 1];
    float a2 = anc[4 * i + 2], a3 = anc[4 * i + 3];
    float o0 = off[4 * i + 0], o1 = off[4 * i + 1];
    float o2 = off[4 * i + 2], o3 = off[4 * i + 3];

    float ah  = __fsub_rn(a2, a0);
    float aw  = __fsub_rn(a3, a1);
    float acy = __fadd_rn(a0, __fmul_rn(0.5f, ah));
    float acx = __fadd_rn(a1, __fmul_rn(0.5f, aw));
    float cy  = __fadd_rn(__fmul_rn(o0, ah), acy);
    float cx  = __fadd_rn(__fmul_rn(o1, aw), acx);
    float h   = __fmul_rn(expf(o2), ah);
    float w   = __fmul_rn(expf(o3), aw);

    float y1 = __fsub_rn(cy, __fmul_rn(0.5f, h));
    float x1 = __fsub_rn(cx, __fmul_rn(0.5f, w));
    float y2 = __fadd_rn(cy, __fmul_rn(0.5f, h));
    float x2 = __fadd_rn(cx, __fmul_rn(0.5f, w));

    y1 = fminf(fmaxf(y1, 0.0f), H);
    x1 = fminf(fmaxf(x1, 0.0f), W);
    y2 = fminf(fmaxf(y2, 0.0f), H);
    x2 = fminf(fmaxf(x2, 0.0f), W);

    float rh = __fsub_rn(y2, y1);
    float rw = __fsub_rn(x2, x1);
    bool valid = (rh >= minsz) && (rw >= minsz);

    unsigned key = 0u;
    if (valid) {
        unsigned u = __float_as_uint(sc[i]);
        key = (u & 0x80000000u) ? ~u : (u | 0x80000000u);
        if (key == 0u) key = 1u;
    }
    g_keys[i]  = key;
    g_boxes[i] = make_float4(y1, x1, y2, x2);
    if (key) atomicAdd(&g_hist1[key >> 16], 1);
}

// -------------------- K2: find threshold bin (16 high bits) ----------------
__global__ void k_find1() {
    __shared__ int part[1024];
    int t = threadIdx.x;
    const int4* h4 = (const int4*)g_hist1;
    int s = 0;
#pragma unroll
    for (int k = 0; k < 16; k++) {
        int4 v = h4[t * 16 + k];
        s += v.x + v.y + v.z + v.w;
    }
    part[t] = s;
    __syncthreads();
    for (int offs = 1; offs < 1024; offs <<= 1) {
        int v = part[t] + ((t + offs < 1024) ? part[t + offs] : 0);
        __syncthreads();
        part[t] = v;
        __syncthreads();
    }
    int Sincl = part[t];
    int Sexcl = Sincl - s;
    if (t == 0 && part[0] < NPRE) g_flag = 1;
    if (Sexcl < NPRE && Sincl >= NPRE) {
        int base = t * 64;
        int cum = Sexcl;
        for (int b = base + 63; b >= base; b--) {
            int hb = g_hist1[b];
            cum += hb;
            if (cum >= NPRE) {
                g_T  = (unsigned)b;
                g_C1 = cum - hb;
                break;
            }
        }
    }
}

// ------------------ K3: second-level histogram (16 low bits) ---------------
__global__ void k_hist2(int n) {
    int i = blockIdx.x * blockDim.x + threadIdx.x;
    if (i >= n) return;
    unsigned key = g_keys[i];
    if (key && (key >> 16) == g_T) atomicAdd(&g_hist2[key & 0xFFFFu], 1);
}

// ----------------------- K4: exact 32-bit K-th key -------------------------
__global__ void k_find2() {
    if (g_flag) return;
    __shared__ int part[1024];
    int t = threadIdx.x;
    int C1 = g_C1;
    const int4* h4 = (const int4*)g_hist2;
    int s = 0;
#pragma unroll
    for (int k = 0; k < 16; k++) {
        int4 v = h4[t * 16 + k];
        s += v.x + v.y + v.z + v.w;
    }
    part[t] = s;
    __syncthreads();
    for (int offs = 1; offs < 1024; offs <<= 1) {
        int v = part[t] + ((t + offs < 1024) ? part[t + offs] : 0);
        __syncthreads();
        part[t] = v;
        __syncthreads();
    }
    int Sincl = part[t];
    int Sexcl = Sincl - s;
    if (C1 + Sexcl < NPRE && C1 + Sincl >= NPRE) {
        int base = t * 64;
        int cum = C1 + Sexcl;
        for (int b = base + 63; b >= base; b--) {
            cum += g_hist2[b];
            if (cum >= NPRE) {
                g_kthKey = (g_T << 16) | (unsigned)b;
                break;
            }
        }
    }
}

// ----------------------------- K5: gather ----------------------------------
__global__ void k_gather(int n) {
    int i = blockIdx.x * blockDim.x + threadIdx.x;
    if (i >= n) return;
    unsigned key = g_keys[i];
    if (key && key >= g_kthKey) {
        int p = atomicAdd(&g_candCount, 1);
        if (p < CAP) {
            // composite: score key desc, then index asc (top_k tie-break)
            g_cand[p] = ((unsigned long long)key << 32) |
                        (unsigned long long)(0xFFFFFFFFu - (unsigned)i);
        }
    }
}

// --------- K6: brute-force rank (keys unique) + scatter boxes/areas --------
// rank_i = #{j : key_j > key_i}  ->  exact descending position. 64 blocks.
__global__ void __launch_bounds__(256) k_rank() {
    __shared__ unsigned long long tile[256];
    int m = g_candCount; if (m > CAP) m = CAP;
    int i = blockIdx.x * 256 + threadIdx.x;
    unsigned long long my = (i < m) ? g_cand[i] : 0ull;

    int rank = 0;
    int ntiles = (m + 255) >> 8;
    for (int t = 0; t < ntiles; t++) {
        int j = t * 256 + threadIdx.x;
        tile[threadIdx.x] = (j < m) ? g_cand[j] : 0ull;   // pad 0 never > valid key
        __syncthreads();
#pragma unroll 16
        for (int k = 0; k < 256; k++) rank += (tile[k] > my) ? 1 : 0;
        __syncthreads();
    }

    if (i < m && rank < NPRE) {
        unsigned idx = 0xFFFFFFFFu - (unsigned)my;
        float4 b = g_boxes[idx];
        g_topBox[rank]  = b;
        g_topArea[rank] = __fmul_rn(__fsub_rn(b.z, b.x), __fsub_rn(b.w, b.y));
    }
    if (i == 0) g_validTop = (m < NPRE) ? m : NPRE;
}

// --------------------------- IoU (reference-exact) -------------------------
__device__ __forceinline__ bool iou_gt(float4 a, float aa, float4 b, float ab) {
    float ty = fmaxf(a.x, b.x);
    float tx = fmaxf(a.y, b.y);
    float by = fminf(a.z, b.z);
    float bx = fminf(a.w, b.w);
    float hh = fmaxf(__fsub_rn(by, ty), 0.0f);
    float ww = fmaxf(__fsub_rn(bx, tx), 0.0f);
    float inter = __fmul_rn(hh, ww);
    float uni = __fsub_rn(__fadd_rn(aa, ab), inter);
    float iou = __fdiv_rn(inter, fmaxf(uni, 1e-9f));
    return iou > NMS_T;
}

// --------- K7: parallel suppression mask (64x64 tiles, full words) ---------
__global__ void k_mask(int rb0, int gated) {
    if (gated && !g_needMore) return;
    int rb = rb0 + blockIdx.y;
    int cb = blockIdx.x;
    if (cb > rb) return;

    __shared__ float4 cB[64];
    __shared__ float  cA[64];
    int t = threadIdx.x;
    cB[t] = g_topBox[cb * 64 + t];
    cA[t] = g_topArea[cb * 64 + t];
    __syncthreads();

    int row = rb * 64 + t;
    if (row >= NPRE) return;
    float4 rbx = g_topBox[row];
    float  ra  = g_topArea[row];

    unsigned long long word = 0ull;
    int jmax = (cb == rb) ? t : 64;   // strictly j < i
    for (int j = 0; j < jmax; j++)
        if (iou_gt(rbx, ra, cB[j], cA[j])) word |= (1ull << j);
    g_mask[(size_t)row * WPR + cb] = word;
}

// ---------- K8: greedy resolve over precomputed mask (IoU-free) ------------
__global__ void __launch_bounds__(1024, 1) k_resolve(int stage, float* __restrict__ out) {
    if (stage && !g_needMore) return;

    __shared__ unsigned long long keptMask[WPR];
    __shared__ unsigned long long diag[64];
    __shared__ int                supPrev[64];
    __shared__ unsigned long long sKl;
    __shared__ int                sKept;

    int tid  = threadIdx.x;
    int lane = tid & 31;
    int warp = tid >> 5;   // 32 warps

    int vt = g_validTop;
    int start = stage ? B1 : 0;
    int end   = stage ? vt : (vt < B1 ? vt : B1);
    int kept  = stage ? g_kept : 0;

    if (stage) { for (int w = tid; w < WPR; w += 1024) keptMask[w] = g_keptMaskG[w]; }
    else       { for (int w = tid; w < WPR; w += 1024) keptMask[w] = 0ull; }
    __syncthreads();

    for (int base = start; base < end && kept < NPOST; base += 64) {
        int cn = end - base; if (cn > 64) cn = 64;
        int cw = base >> 6;

        // suppressed-by-previously-kept: AND mask row with keptMask words
        for (int r = warp; r < cn; r += 32) {
            const unsigned long long* rowp = &g_mask[(size_t)(base + r) * WPR];
            bool any = false;
            for (int w = lane; w < cw; w += 32)
                any |= (__ldg(&rowp[w]) & keptMask[w]) != 0ull;
            unsigned bal = __ballot_sync(0xffffffffu, any);
            if (lane == 0) supPrev[r] = (bal != 0u);
        }
        if (tid < cn) diag[tid] = g_mask[(size_t)(base + tid) * WPR + cw];
        __syncthreads();

        // exact sequential greedy within the 64-chunk
        if (tid == 0) {
            unsigned long long kl = 0ull;
            int kc = kept;
            for (int i = 0; i < cn && kc < NPOST; i++) {
                if (!supPrev[i] && !(diag[i] & kl)) { kl |= (1ull << i); kc++; }
            }
            sKl = kl; sKept = kc;
            keptMask[cw] = kl;
        }
        __syncthreads();

        unsigned long long kl = sKl;
        if (tid < cn && ((kl >> tid) & 1ull)) {
            int pos = kept + __popcll(kl & ((1ull << tid) - 1ull));
            ((float4*)out)[pos] = g_topBox[base + tid];
        }
        __syncthreads();
        kept = sKept;
        __syncthreads();
    }

    if (tid == 0) {
        g_kept = kept;
        if (stage == 0) g_needMore = (kept < NPOST && vt > B1) ? 1 : 0;
    }
    for (int w = tid; w < WPR; w += 1024) g_keptMaskG[w] = keptMask[w];
}

// ------------------------------- launcher ----------------------------------
extern "C" void kernel_launch(void* const* d_in, const int* in_sizes, int n_in,
                              void* d_out, int out_size) {
    const float* anchors = (const float*)d_in[0];
    const float* offsets = (const float*)d_in[1];
    const float* scores  = (const float*)d_in[2];
    const int*   ph      = (const int*)d_in[3];
    const int*   pw      = (const int*)d_in[4];
    const int*   ps      = (const int*)d_in[5];
    float* out = (float*)d_out;

    int n = in_sizes[2];
    if (n > NMAX) n = NMAX;
    int nb = (n + 255) / 256;

    k_zero<<<128, 256>>>(out);
    k_decode<<<nb, 256>>>(anchors, offsets, scores, ph, pw, ps, n);
    k_find1<<<1, 1024>>>();
    k_hist2<<<nb, 256>>>(n);
    k_find2<<<1, 1024>>>();
    k_gather<<<nb, 256>>>(n);
    k_rank<<<CAP / 256, 256>>>();

    // stage-1 NMS mask: first B1 ranks (always)
    k_mask<<<dim3(B1 / 64, B1 / 64), 64>>>(0, 0);
    k_resolve<<<1, 1024>>>(0, out);

    // stage-2 (rare): remaining ranks, gated on g_needMore
    k_mask<<<dim3(WPR, WPR - B1 / 64), 64>>>(B1 / 64, 1);
    k_resolve<<<1, 1024>>>(1, out);
}